// round 2
// baseline (speedup 1.0000x reference)
#include <cuda_runtime.h>

// Problem constants
#define CB    128          // input channels
#define HH    56
#define WW    56
#define NPIX  3136         // 56*56
#define BATCH 8
#define NTOT  25088        // BATCH * NPIX
#define KTOT  1152         // CB * 9
#define OUTC  128

// Scratch
__device__ float g_off[BATCH * 18 * NPIX];          // offset conv output
__device__ float g_col[(size_t)KTOT * NTOT];        // im2col-after-deform, ~115.6 MB

// ---------------------------------------------------------------------------
// Kernel 1 (v2): offset prediction conv (128 -> 18 ch, 3x3, pad 1)
// Block = (b, 4-row tile): 112 blocks x 504 threads.
// Thread = (j in 18, row in 4, 8-px strip in 7). Per channel: x tile + weights
// staged in smem; weights + row window in regs -> 72 FMA per ~12 LDS.128.
// ---------------------------------------------------------------------------
#define YT  4
#define CCH 2
#define XS_W 68   // padded row stride (floats), 16B-aligned

__global__ __launch_bounds__(504) void offset_conv_kernel(
        const float* __restrict__ x,
        const float* __restrict__ w,
        const float* __restrict__ bias) {
    __shared__ float xs[CCH][YT + 2][XS_W];
    __shared__ float ws[CCH][18][12];

    int b  = blockIdx.x / 14;
    int yt = blockIdx.x % 14;
    int y0 = yt * YT;
    int tid = threadIdx.x;

    // zero smem once (halo columns must stay zero)
    for (int i = tid; i < CCH * (YT + 2) * XS_W; i += 504) ((float*)xs)[i] = 0.f;
    __syncthreads();

    int strip = tid % 7;
    int row   = (tid / 7) % YT;
    int j     = tid / 28;      // 0..17

    float acc[8];
    #pragma unroll
    for (int i = 0; i < 8; ++i) acc[i] = 0.f;

    const float* xb = x + (size_t)b * CB * NPIX;

    for (int c0 = 0; c0 < CB; c0 += CCH) {
        __syncthreads();
        // load x tiles: CCH * 6 * 56 = 672 interior elements
        for (int e = tid; e < CCH * (YT + 2) * WW; e += 504) {
            int cc  = e / ((YT + 2) * WW);
            int r2  = e % ((YT + 2) * WW);
            int ry  = r2 / WW;
            int col = r2 % WW;
            int yy  = y0 - 1 + ry;
            float v = 0.f;
            if (yy >= 0 && yy < HH) v = __ldg(xb + (size_t)(c0 + cc) * NPIX + yy * WW + col);
            xs[cc][ry][col + 1] = v;
        }
        // load weights: CCH * 18 * 9 = 324 elements
        for (int e = tid; e < CCH * 18 * 9; e += 504) {
            int cc = e / 162;
            int r2 = e % 162;
            int jj = r2 / 9;
            int t  = r2 % 9;
            ws[cc][jj][t] = __ldg(w + jj * KTOT + (c0 + cc) * 9 + t);
        }
        __syncthreads();

        #pragma unroll
        for (int cc = 0; cc < CCH; ++cc) {
            float wr[12];
            {
                float4 w0 = *(const float4*)&ws[cc][j][0];
                float4 w1 = *(const float4*)&ws[cc][j][4];
                float4 w2 = *(const float4*)&ws[cc][j][8];
                wr[0] = w0.x; wr[1] = w0.y; wr[2] = w0.z; wr[3] = w0.w;
                wr[4] = w1.x; wr[5] = w1.y; wr[6] = w1.z; wr[7] = w1.w;
                wr[8] = w2.x; wr[9] = w2.y; wr[10] = w2.z; wr[11] = w2.w;
            }
            #pragma unroll
            for (int ky = 0; ky < 3; ++ky) {
                float rv[12];
                const float* rp = &xs[cc][row + ky][strip * 8];
                float4 r0 = *(const float4*)(rp);
                float4 r1 = *(const float4*)(rp + 4);
                float4 r2 = *(const float4*)(rp + 8);
                rv[0] = r0.x; rv[1] = r0.y; rv[2] = r0.z;  rv[3] = r0.w;
                rv[4] = r1.x; rv[5] = r1.y; rv[6] = r1.z;  rv[7] = r1.w;
                rv[8] = r2.x; rv[9] = r2.y; rv[10] = r2.z; rv[11] = r2.w;
                #pragma unroll
                for (int kx = 0; kx < 3; ++kx) {
                    float wv = wr[ky * 3 + kx];
                    #pragma unroll
                    for (int i = 0; i < 8; ++i)
                        acc[i] = fmaf(wv, rv[i + kx], acc[i]);
                }
            }
        }
    }

    float bj = __ldg(bias + j);
    float* op = g_off + (size_t)(b * 18 + j) * NPIX + (y0 + row) * WW + strip * 8;
    #pragma unroll
    for (int i = 0; i < 8; ++i) op[i] = acc[i] + bj;
}

// ---------------------------------------------------------------------------
// Kernel 2: deformable bilinear sampling -> col[k = c*9+n][np = b*3136+pix]
// ---------------------------------------------------------------------------
__global__ void sample_kernel(const float* __restrict__ x) {
    int t = blockIdx.x * blockDim.x + threadIdx.x;
    if (t >= BATCH * 9 * NPIX) return;
    int pix = t % NPIX;
    int n   = (t / NPIX) % 9;
    int b   = t / (NPIX * 9);
    int y   = pix / WW, xw = pix % WW;

    float off_y = g_off[(size_t)(b * 18 + n) * NPIX + pix];
    float off_x = g_off[(size_t)(b * 18 + n + 9) * NPIX + pix];

    float p_y = (float)(y + n / 3) + off_y;
    float p_x = (float)(xw + n % 3) + off_x;

    float qy = floorf(p_y), qx = floorf(p_x);
    float qlt_y = fminf(fmaxf(qy, 0.f), 57.f);
    float qlt_x = fminf(fmaxf(qx, 0.f), 57.f);
    float qrb_y = fminf(fmaxf(qy + 1.f, 0.f), 57.f);
    float qrb_x = fminf(fmaxf(qx + 1.f, 0.f), 57.f);
    float py = fminf(fmaxf(p_y, 0.f), 57.f);
    float px = fminf(fmaxf(p_x, 0.f), 57.f);

    float g_lt = (1.f - (py - qlt_y)) * truncf(1.f - (px - qlt_x));
    float g_rb = (1.f - (qrb_y - py)) * truncf(1.f - (qrb_x - px));
    float g_lb = (1.f - (py - qlt_y)) * (1.f - (qrb_x - px));
    float g_rt = (1.f - (qrb_y - py)) * (1.f - (px - qlt_x));

    int iy_lt = (int)qlt_y, ix_lt = (int)qlt_x;
    int iy_rb = (int)qrb_y, ix_rb = (int)qrb_x;

    int o0 = (iy_lt - 1) * WW + (ix_lt - 1);
    int o1 = (iy_rb - 1) * WW + (ix_rb - 1);
    int o2 = (iy_lt - 1) * WW + (ix_rb - 1);
    int o3 = (iy_rb - 1) * WW + (ix_lt - 1);

    bool vy_lt = (iy_lt >= 1) && (iy_lt <= 56);
    bool vx_lt = (ix_lt >= 1) && (ix_lt <= 56);
    bool vy_rb = (iy_rb >= 1) && (iy_rb <= 56);
    bool vx_rb = (ix_rb >= 1) && (ix_rb <= 56);

    float w0 = (vy_lt && vx_lt) ? g_lt : 0.f;
    float w1 = (vy_rb && vx_rb) ? g_rb : 0.f;
    float w2 = (vy_lt && vx_rb) ? g_lb : 0.f;
    float w3 = (vy_rb && vx_lt) ? g_rt : 0.f;

    const float* xb = x + (size_t)b * CB * NPIX;
    float* colp = g_col + (size_t)n * NTOT + (size_t)b * NPIX + pix;

    for (int c = 0; c < CB; ++c) {
        const float* xc = xb + (size_t)c * NPIX;
        float v = 0.f;
        if (w0 != 0.f) v = fmaf(w0, __ldg(xc + o0), v);
        if (w1 != 0.f) v = fmaf(w1, __ldg(xc + o1), v);
        if (w2 != 0.f) v = fmaf(w2, __ldg(xc + o2), v);
        if (w3 != 0.f) v = fmaf(w3, __ldg(xc + o3), v);
        colp[(size_t)c * 9 * NTOT] = v;
    }
}

// ---------------------------------------------------------------------------
// Kernel 3: SGEMM with register-prefetch double buffering
// C[o][np] = sum_k A[o][k] * col[k][np],  128x64 tile, 128 threads, 8x8 micro
// ---------------------------------------------------------------------------
#define BM 128
#define BN 64
#define BK 16

__global__ __launch_bounds__(128) void gemm_kernel(const float* __restrict__ A,
                                                   float* __restrict__ out) {
    __shared__ float As[BK][BM];
    __shared__ float Bs[BK][BN];

    int n0  = blockIdx.x * BN;
    int tid = threadIdx.x;
    int tm  = tid / 8;   // 0..15
    int tn  = tid % 8;   // 0..7

    float acc[8][8];
    #pragma unroll
    for (int i = 0; i < 8; ++i)
        #pragma unroll
        for (int j = 0; j < 8; ++j) acc[i][j] = 0.f;

    float pa[16], pb[8];

    // prefetch first tile into regs
    #pragma unroll
    for (int i = 0; i < 16; ++i) {
        int e = tid + i * 128;
        pa[i] = __ldg(A + (size_t)(e / BK) * KTOT + (e % BK));
    }
    #pragma unroll
    for (int i = 0; i < 8; ++i) {
        int e = tid + i * 128;
        pb[i] = g_col[(size_t)(e / BN) * NTOT + n0 + (e % BN)];
    }

    for (int k0 = 0; k0 < KTOT; k0 += BK) {
        // commit regs to smem
        #pragma unroll
        for (int i = 0; i < 16; ++i) {
            int e = tid + i * 128;
            As[e % BK][e / BK] = pa[i];
        }
        #pragma unroll
        for (int i = 0; i < 8; ++i) {
            int e = tid + i * 128;
            Bs[e / BN][e % BN] = pb[i];
        }
        __syncthreads();

        // prefetch next tile while computing current
        if (k0 + BK < KTOT) {
            #pragma unroll
            for (int i = 0; i < 16; ++i) {
                int e = tid + i * 128;
                pa[i] = __ldg(A + (size_t)(e / BK) * KTOT + k0 + BK + (e % BK));
            }
            #pragma unroll
            for (int i = 0; i < 8; ++i) {
                int e = tid + i * 128;
                pb[i] = g_col[(size_t)(k0 + BK + e / BN) * NTOT + n0 + (e % BN)];
            }
        }

        #pragma unroll
        for (int kk = 0; kk < BK; ++kk) {
            float4 a0 = *(const float4*)&As[kk][tm * 4];
            float4 a1 = *(const float4*)&As[kk][64 + tm * 4];
            float4 b0 = *(const float4*)&Bs[kk][tn * 4];
            float4 b1 = *(const float4*)&Bs[kk][32 + tn * 4];
            float a[8]  = {a0.x, a0.y, a0.z, a0.w, a1.x, a1.y, a1.z, a1.w};
            float bf[8] = {b0.x, b0.y, b0.z, b0.w, b1.x, b1.y, b1.z, b1.w};
            #pragma unroll
            for (int i = 0; i < 8; ++i)
                #pragma unroll
                for (int jj = 0; jj < 8; ++jj)
                    acc[i][jj] = fmaf(a[i], bf[jj], acc[i][jj]);
        }
        __syncthreads();
    }

    #pragma unroll
    for (int i = 0; i < 8; ++i) {
        int m = (i < 4) ? (tm * 4 + i) : (64 + tm * 4 + (i - 4));
        #pragma unroll
        for (int jj = 0; jj < 8; ++jj) {
            int nl  = (jj < 4) ? (tn * 4 + jj) : (32 + tn * 4 + (jj - 4));
            int np  = n0 + nl;
            int b   = np / NPIX;
            int pix = np % NPIX;
            out[(size_t)b * OUTC * NPIX + (size_t)m * NPIX + pix] = acc[i][jj];
        }
    }
}

// ---------------------------------------------------------------------------
extern "C" void kernel_launch(void* const* d_in, const int* in_sizes, int n_in,
                              void* d_out, int out_size) {
    const float* x  = (const float*)d_in[0];   // [8,128,56,56]
    const float* ow = (const float*)d_in[1];   // [18,128,3,3]
    const float* ob = (const float*)d_in[2];   // [18]
    const float* cw = (const float*)d_in[3];   // [128,128,3,3]
    float* out = (float*)d_out;                // [8,128,56,56]

    offset_conv_kernel<<<BATCH * 14, 504>>>(x, ow, ob);
    sample_kernel<<<(BATCH * 9 * NPIX + 255) / 256, 256>>>(x);
    gemm_kernel<<<NTOT / BN, 128>>>(cw, out);
}

// round 3
// speedup vs baseline: 1.5118x; 1.5118x over previous
#include <cuda_runtime.h>

// Problem constants
#define CB    128
#define HH    56
#define WW    56
#define NPIX  3136
#define BATCH 8
#define NTOT  25088        // BATCH * NPIX
#define KTOT  1152         // CB * 9
#define OUTC  128

// Scratch
__device__ float g_off[BATCH * 18 * NPIX];
__device__ float g_col[(size_t)KTOT * NTOT];   // ~115.6 MB

// ---------------------------------------------------------------------------
// Kernel 1 (v3): offset conv (128 -> 18ch, 3x3, pad 1)
// Block = (b, y): 448 blocks x 128 threads (126 active: j in 18, strip in 7).
// Per 32-channel chunk: 3 input rows + all 18x9 weights staged in smem.
// Thread computes 8 outputs along x; 39 LDS -> 72 FMA per channel.
// ---------------------------------------------------------------------------
#define OC_CCH 32

__global__ __launch_bounds__(128) void offset_conv_kernel(
        const float* __restrict__ x,
        const float* __restrict__ w,
        const float* __restrict__ bias) {
    __shared__ float xs[OC_CCH][3][60];     // 23040 B (cols 0,57..59 stay zero)
    __shared__ float ws[OC_CCH][18][9];     // 20736 B

    int b   = blockIdx.x / HH;
    int y   = blockIdx.x % HH;
    int tid = threadIdx.x;
    int j     = tid / 7;        // 0..17
    int strip = tid % 7;        // 0..6
    bool active = tid < 126;

    // zero halo columns once (never overwritten by loads)
    for (int e = tid; e < OC_CCH * 3; e += 128) {
        int cc = e / 3, r = e % 3;
        xs[cc][r][0] = 0.f; xs[cc][r][57] = 0.f;
        xs[cc][r][58] = 0.f; xs[cc][r][59] = 0.f;
    }

    float acc[8];
    #pragma unroll
    for (int i = 0; i < 8; ++i) acc[i] = 0.f;

    const float* xb = x + (size_t)b * CB * NPIX;

    for (int c0 = 0; c0 < CB; c0 += OC_CCH) {
        __syncthreads();
        // x tile: 32ch x 3rows x 56cols
        for (int e = tid; e < OC_CCH * 3 * WW; e += 128) {
            int cc  = e / (3 * WW);
            int r2  = e % (3 * WW);
            int r   = r2 / WW;
            int col = r2 % WW;
            int yy  = y - 1 + r;
            float v = 0.f;
            if (yy >= 0 && yy < HH)
                v = __ldg(xb + (size_t)(c0 + cc) * NPIX + yy * WW + col);
            xs[cc][r][col + 1] = v;
        }
        // weights: 32ch x 18j x 9
        for (int e = tid; e < OC_CCH * 162; e += 128) {
            int cc = e / 162;
            int r2 = e % 162;
            ws[cc][r2 / 9][r2 % 9] = __ldg(w + (r2 / 9) * KTOT + (c0 + cc) * 9 + (r2 % 9));
        }
        __syncthreads();

        if (active) {
            #pragma unroll 4
            for (int cc = 0; cc < OC_CCH; ++cc) {
                float wr[9];
                #pragma unroll
                for (int t = 0; t < 9; ++t) wr[t] = ws[cc][j][t];
                #pragma unroll
                for (int ky = 0; ky < 3; ++ky) {
                    float rv[10];
                    #pragma unroll
                    for (int i = 0; i < 10; ++i) rv[i] = xs[cc][ky][strip * 8 + i];
                    #pragma unroll
                    for (int kx = 0; kx < 3; ++kx) {
                        float wv = wr[ky * 3 + kx];
                        #pragma unroll
                        for (int i = 0; i < 8; ++i)
                            acc[i] = fmaf(wv, rv[i + kx], acc[i]);
                    }
                }
            }
        }
    }

    if (active) {
        float bj = __ldg(bias + j);
        float* op = g_off + (size_t)(b * 18 + j) * NPIX + y * WW + strip * 8;
        #pragma unroll
        for (int i = 0; i < 8; ++i) op[i] = acc[i] + bj;
    }
}

// ---------------------------------------------------------------------------
// Kernel 2: deformable bilinear sampling -> col[k = c*9+n][np = b*3136+pix]
// ---------------------------------------------------------------------------
__global__ void sample_kernel(const float* __restrict__ x) {
    int t = blockIdx.x * blockDim.x + threadIdx.x;
    if (t >= BATCH * 9 * NPIX) return;
    int pix = t % NPIX;
    int n   = (t / NPIX) % 9;
    int b   = t / (NPIX * 9);
    int y   = pix / WW, xw = pix % WW;

    float off_y = g_off[(size_t)(b * 18 + n) * NPIX + pix];
    float off_x = g_off[(size_t)(b * 18 + n + 9) * NPIX + pix];

    float p_y = (float)(y + n / 3) + off_y;
    float p_x = (float)(xw + n % 3) + off_x;

    float qy = floorf(p_y), qx = floorf(p_x);
    float qlt_y = fminf(fmaxf(qy, 0.f), 57.f);
    float qlt_x = fminf(fmaxf(qx, 0.f), 57.f);
    float qrb_y = fminf(fmaxf(qy + 1.f, 0.f), 57.f);
    float qrb_x = fminf(fmaxf(qx + 1.f, 0.f), 57.f);
    float py = fminf(fmaxf(p_y, 0.f), 57.f);
    float px = fminf(fmaxf(p_x, 0.f), 57.f);

    float g_lt = (1.f - (py - qlt_y)) * truncf(1.f - (px - qlt_x));
    float g_rb = (1.f - (qrb_y - py)) * truncf(1.f - (qrb_x - px));
    float g_lb = (1.f - (py - qlt_y)) * (1.f - (qrb_x - px));
    float g_rt = (1.f - (qrb_y - py)) * (1.f - (px - qlt_x));

    int iy_lt = (int)qlt_y, ix_lt = (int)qlt_x;
    int iy_rb = (int)qrb_y, ix_rb = (int)qrb_x;

    int o0 = (iy_lt - 1) * WW + (ix_lt - 1);
    int o1 = (iy_rb - 1) * WW + (ix_rb - 1);
    int o2 = (iy_lt - 1) * WW + (ix_rb - 1);
    int o3 = (iy_rb - 1) * WW + (ix_lt - 1);

    bool vy_lt = (iy_lt >= 1) && (iy_lt <= 56);
    bool vx_lt = (ix_lt >= 1) && (ix_lt <= 56);
    bool vy_rb = (iy_rb >= 1) && (iy_rb <= 56);
    bool vx_rb = (ix_rb >= 1) && (ix_rb <= 56);

    float w0 = (vy_lt && vx_lt) ? g_lt : 0.f;
    float w1 = (vy_rb && vx_rb) ? g_rb : 0.f;
    float w2 = (vy_lt && vx_rb) ? g_lb : 0.f;
    float w3 = (vy_rb && vx_lt) ? g_rt : 0.f;

    const float* xb = x + (size_t)b * CB * NPIX;
    float* colp = g_col + (size_t)n * NTOT + (size_t)b * NPIX + pix;

    for (int c = 0; c < CB; ++c) {
        const float* xc = xb + (size_t)c * NPIX;
        float v = 0.f;
        if (w0 != 0.f) v = fmaf(w0, __ldg(xc + o0), v);
        if (w1 != 0.f) v = fmaf(w1, __ldg(xc + o1), v);
        if (w2 != 0.f) v = fmaf(w2, __ldg(xc + o2), v);
        if (w3 != 0.f) v = fmaf(w3, __ldg(xc + o3), v);
        colp[(size_t)c * 9 * NTOT] = v;
    }
}

// ---------------------------------------------------------------------------
// Kernel 3: SGEMM (R1 form — no reg prefetch)
// C[o][np] = sum_k A[o][k] * col[k][np], 128x64 tile, 128 threads, 8x8 micro
// ---------------------------------------------------------------------------
#define BM 128
#define BN 64
#define BK 16

__global__ __launch_bounds__(128) void gemm_kernel(const float* __restrict__ A,
                                                   float* __restrict__ out) {
    __shared__ float As[BK][BM];
    __shared__ float Bs[BK][BN];

    int n0  = blockIdx.x * BN;
    int tid = threadIdx.x;
    int tm  = tid / 8;
    int tn  = tid % 8;

    float acc[8][8];
    #pragma unroll
    for (int i = 0; i < 8; ++i)
        #pragma unroll
        for (int j = 0; j < 8; ++j) acc[i][j] = 0.f;

    for (int k0 = 0; k0 < KTOT; k0 += BK) {
        #pragma unroll
        for (int i = 0; i < 16; ++i) {
            int e  = tid + i * 128;
            int m  = e / BK;
            int kk = e % BK;
            As[kk][m] = __ldg(A + (size_t)m * KTOT + k0 + kk);
        }
        #pragma unroll
        for (int i = 0; i < 8; ++i) {
            int e  = tid + i * 128;
            int kk = e / BN;
            int nn = e % BN;
            Bs[kk][nn] = g_col[(size_t)(k0 + kk) * NTOT + n0 + nn];
        }
        __syncthreads();

        #pragma unroll
        for (int kk = 0; kk < BK; ++kk) {
            float4 a0 = *(const float4*)&As[kk][tm * 4];
            float4 a1 = *(const float4*)&As[kk][64 + tm * 4];
            float4 b0 = *(const float4*)&Bs[kk][tn * 4];
            float4 b1 = *(const float4*)&Bs[kk][32 + tn * 4];
            float a[8]  = {a0.x, a0.y, a0.z, a0.w, a1.x, a1.y, a1.z, a1.w};
            float bf[8] = {b0.x, b0.y, b0.z, b0.w, b1.x, b1.y, b1.z, b1.w};
            #pragma unroll
            for (int i = 0; i < 8; ++i)
                #pragma unroll
                for (int jj = 0; jj < 8; ++jj)
                    acc[i][jj] = fmaf(a[i], bf[jj], acc[i][jj]);
        }
        __syncthreads();
    }

    #pragma unroll
    for (int i = 0; i < 8; ++i) {
        int m = (i < 4) ? (tm * 4 + i) : (64 + tm * 4 + (i - 4));
        #pragma unroll
        for (int jj = 0; jj < 8; ++jj) {
            int nl  = (jj < 4) ? (tn * 4 + jj) : (32 + tn * 4 + (jj - 4));
            int np  = n0 + nl;
            int b   = np / NPIX;
            int pix = np % NPIX;
            out[(size_t)b * OUTC * NPIX + (size_t)m * NPIX + pix] = acc[i][jj];
        }
    }
}

// ---------------------------------------------------------------------------
extern "C" void kernel_launch(void* const* d_in, const int* in_sizes, int n_in,
                              void* d_out, int out_size) {
    const float* x  = (const float*)d_in[0];
    const float* ow = (const float*)d_in[1];
    const float* ob = (const float*)d_in[2];
    const float* cw = (const float*)d_in[3];
    float* out = (float*)d_out;

    offset_conv_kernel<<<BATCH * HH, 128>>>(x, ow, ob);
    sample_kernel<<<(BATCH * 9 * NPIX + 255) / 256, 256>>>(x);
    gemm_kernel<<<NTOT / BN, 128>>>(cw, out);
}

// round 5
// speedup vs baseline: 2.4283x; 1.6062x over previous
#include <cuda_runtime.h>
#include <cstdint>

// Problem constants
#define CB    128
#define HH    56
#define WW    56
#define NPIX  3136
#define BATCH 8
#define NTOT  25088        // BATCH * NPIX
#define KTOT  1152         // CB * 9
#define OUTC  128

// Scratch
__device__ float g_off[BATCH * 18 * NPIX];
__device__ float g_colT[(size_t)NTOT * KTOT];   // [np][k], tf32-rounded, ~115.6 MB
__device__ float g_wt32[(size_t)OUTC * KTOT];   // tf32-rounded weights

__device__ __forceinline__ float to_tf32(float f) {
    uint32_t u;
    asm("cvt.rna.tf32.f32 %0, %1;" : "=r"(u) : "f"(f));
    return __uint_as_float(u);
}
__device__ __forceinline__ uint32_t smem_u32(const void* p) {
    uint32_t a;
    asm("{ .reg .u64 t; cvta.to.shared.u64 t, %1; cvt.u32.u64 %0, t; }" : "=r"(a) : "l"(p));
    return a;
}
#define CP_ASYNC_CA(dst, src) \
    asm volatile("cp.async.ca.shared.global [%0], [%1], 16;" :: "r"(dst), "l"(src))
#define CP_ASYNC_CG(dst, src) \
    asm volatile("cp.async.cg.shared.global [%0], [%1], 16;" :: "r"(dst), "l"(src))
#define CP_COMMIT() asm volatile("cp.async.commit_group;" ::: "memory")
#define CP_WAIT(n)  asm volatile("cp.async.wait_group %0;" :: "n"(n) : "memory")

// ---------------------------------------------------------------------------
// Kernel 0: round conv weights to tf32
// ---------------------------------------------------------------------------
__global__ void round_w_kernel(const float* __restrict__ w) {
    int i = blockIdx.x * blockDim.x + threadIdx.x;
    if (i < OUTC * KTOT) g_wt32[i] = to_tf32(__ldg(w + i));
}

// ---------------------------------------------------------------------------
// Kernel 1: offset conv (R3 form: 448 blocks x 128 threads)
// ---------------------------------------------------------------------------
#define OC_CCH 32

__global__ __launch_bounds__(128) void offset_conv_kernel(
        const float* __restrict__ x,
        const float* __restrict__ w,
        const float* __restrict__ bias) {
    __shared__ float xs[OC_CCH][3][60];
    __shared__ float ws[OC_CCH][18][9];

    int b   = blockIdx.x / HH;
    int y   = blockIdx.x % HH;
    int tid = threadIdx.x;
    int j     = tid / 7;
    int strip = tid % 7;
    bool active = tid < 126;

    for (int e = tid; e < OC_CCH * 3; e += 128) {
        int cc = e / 3, r = e % 3;
        xs[cc][r][0] = 0.f; xs[cc][r][57] = 0.f;
        xs[cc][r][58] = 0.f; xs[cc][r][59] = 0.f;
    }

    float acc[8];
    #pragma unroll
    for (int i = 0; i < 8; ++i) acc[i] = 0.f;

    const float* xb = x + (size_t)b * CB * NPIX;

    for (int c0 = 0; c0 < CB; c0 += OC_CCH) {
        __syncthreads();
        for (int e = tid; e < OC_CCH * 3 * WW; e += 128) {
            int cc  = e / (3 * WW);
            int r2  = e % (3 * WW);
            int r   = r2 / WW;
            int col = r2 % WW;
            int yy  = y - 1 + r;
            float v = 0.f;
            if (yy >= 0 && yy < HH)
                v = __ldg(xb + (size_t)(c0 + cc) * NPIX + yy * WW + col);
            xs[cc][r][col + 1] = v;
        }
        for (int e = tid; e < OC_CCH * 162; e += 128) {
            int cc = e / 162;
            int r2 = e % 162;
            ws[cc][r2 / 9][r2 % 9] = __ldg(w + (r2 / 9) * KTOT + (c0 + cc) * 9 + (r2 % 9));
        }
        __syncthreads();

        if (active) {
            #pragma unroll 4
            for (int cc = 0; cc < OC_CCH; ++cc) {
                float wr[9];
                #pragma unroll
                for (int t = 0; t < 9; ++t) wr[t] = ws[cc][j][t];
                #pragma unroll
                for (int ky = 0; ky < 3; ++ky) {
                    float rv[10];
                    #pragma unroll
                    for (int i = 0; i < 10; ++i) rv[i] = xs[cc][ky][strip * 8 + i];
                    #pragma unroll
                    for (int kx = 0; kx < 3; ++kx) {
                        float wv = wr[ky * 3 + kx];
                        #pragma unroll
                        for (int i = 0; i < 8; ++i)
                            acc[i] = fmaf(wv, rv[i + kx], acc[i]);
                    }
                }
            }
        }
    }

    if (active) {
        float bj = __ldg(bias + j);
        float* op = g_off + (size_t)(b * 18 + j) * NPIX + y * WW + strip * 8;
        #pragma unroll
        for (int i = 0; i < 8; ++i) op[i] = acc[i] + bj;
    }
}

// ---------------------------------------------------------------------------
// Kernel 2: deformable sampling -> colT[np][k] (tf32-rounded), k = c*9+n
// Block = (b, 64-pix tile): 392 blocks x 288 threads
// ---------------------------------------------------------------------------
#define SCC 8

__global__ __launch_bounds__(288) void sample_kernel(const float* __restrict__ x) {
    __shared__ float4 ws4[64][9];
    __shared__ int4   os4[64][9];
    __shared__ __align__(16) float vals[64][SCC * 9];

    int b    = blockIdx.x / 49;
    int tile = blockIdx.x % 49;
    int tid  = threadIdx.x;

    for (int e = tid; e < 576; e += 288) {
        int np_l = e / 9, n = e % 9;
        int pix = tile * 64 + np_l;
        int y = pix / WW, xw = pix % WW;

        float off_y = g_off[(size_t)(b * 18 + n) * NPIX + pix];
        float off_x = g_off[(size_t)(b * 18 + n + 9) * NPIX + pix];

        float p_y = (float)(y + n / 3) + off_y;
        float p_x = (float)(xw + n % 3) + off_x;

        float qy = floorf(p_y), qx = floorf(p_x);
        float qlt_y = fminf(fmaxf(qy, 0.f), 57.f);
        float qlt_x = fminf(fmaxf(qx, 0.f), 57.f);
        float qrb_y = fminf(fmaxf(qy + 1.f, 0.f), 57.f);
        float qrb_x = fminf(fmaxf(qx + 1.f, 0.f), 57.f);
        float py = fminf(fmaxf(p_y, 0.f), 57.f);
        float px = fminf(fmaxf(p_x, 0.f), 57.f);

        float g_lt = (1.f - (py - qlt_y)) * truncf(1.f - (px - qlt_x));
        float g_rb = (1.f - (qrb_y - py)) * truncf(1.f - (qrb_x - px));
        float g_lb = (1.f - (py - qlt_y)) * (1.f - (qrb_x - px));
        float g_rt = (1.f - (qrb_y - py)) * (1.f - (px - qlt_x));

        int iy_lt = (int)qlt_y, ix_lt = (int)qlt_x;
        int iy_rb = (int)qrb_y, ix_rb = (int)qrb_x;

        int o0 = (iy_lt - 1) * WW + (ix_lt - 1);
        int o1 = (iy_rb - 1) * WW + (ix_rb - 1);
        int o2 = (iy_lt - 1) * WW + (ix_rb - 1);
        int o3 = (iy_rb - 1) * WW + (ix_lt - 1);

        bool vy_lt = (iy_lt >= 1) && (iy_lt <= 56);
        bool vx_lt = (ix_lt >= 1) && (ix_lt <= 56);
        bool vy_rb = (iy_rb >= 1) && (iy_rb <= 56);
        bool vx_rb = (ix_rb >= 1) && (ix_rb <= 56);

        float w0 = (vy_lt && vx_lt) ? g_lt : 0.f;
        float w1 = (vy_rb && vx_rb) ? g_rb : 0.f;
        float w2 = (vy_lt && vx_rb) ? g_lb : 0.f;
        float w3 = (vy_rb && vx_lt) ? g_rt : 0.f;

        ws4[np_l][n] = make_float4(w0, w1, w2, w3);
        os4[np_l][n] = make_int4(o0, o1, o2, o3);
    }
    __syncthreads();

    int e0 = tid, e1 = tid + 288;
    float4 w_a = ws4[e0 / 9][e0 % 9]; int4 o_a = os4[e0 / 9][e0 % 9];
    float4 w_b = ws4[e1 / 9][e1 % 9]; int4 o_b = os4[e1 / 9][e1 % 9];
    int ra = e0 / 9, na = e0 % 9;
    int rb = e1 / 9, nb = e1 % 9;

    const float* xb = x + (size_t)b * CB * NPIX;
    float* colT = g_colT + ((size_t)b * NPIX + (size_t)tile * 64) * KTOT;

    for (int c0 = 0; c0 < CB; c0 += SCC) {
        #pragma unroll
        for (int cc = 0; cc < SCC; ++cc) {
            const float* xc = xb + (size_t)(c0 + cc) * NPIX;
            float v = 0.f;
            if (w_a.x != 0.f) v = fmaf(w_a.x, __ldg(xc + o_a.x), v);
            if (w_a.y != 0.f) v = fmaf(w_a.y, __ldg(xc + o_a.y), v);
            if (w_a.z != 0.f) v = fmaf(w_a.z, __ldg(xc + o_a.z), v);
            if (w_a.w != 0.f) v = fmaf(w_a.w, __ldg(xc + o_a.w), v);
            vals[ra][cc * 9 + na] = to_tf32(v);
            float v2 = 0.f;
            if (w_b.x != 0.f) v2 = fmaf(w_b.x, __ldg(xc + o_b.x), v2);
            if (w_b.y != 0.f) v2 = fmaf(w_b.y, __ldg(xc + o_b.y), v2);
            if (w_b.z != 0.f) v2 = fmaf(w_b.z, __ldg(xc + o_b.z), v2);
            if (w_b.w != 0.f) v2 = fmaf(w_b.w, __ldg(xc + o_b.w), v2);
            vals[rb][cc * 9 + nb] = to_tf32(v2);
        }
        __syncthreads();
        for (int i = tid; i < 64 * 18; i += 288) {
            int row = i / 18, f4 = i % 18;
            *(float4*)(colT + (size_t)row * KTOT + c0 * 9 + f4 * 4) = *(float4*)&vals[row][f4 * 4];
        }
        __syncthreads();
    }
}

// ---------------------------------------------------------------------------
// Kernel 3: tf32 mma.sync GEMM.  D[o][np] = sum_k W[o][k] * colT[np][k]
// Block 256 thr (8 warps, 4x2): tile 128(M) x 128(N) x 32(K), warp 32x64.
// Smem rows padded to 36 floats -> conflict-free fragment LDS.
// cp.async 2-stage double buffer.
// ---------------------------------------------------------------------------
#define GBN 128
#define GBK 32
#define GSTAGES (KTOT / GBK)    // 36
#define ROWF 36                 // floats per smem row
#define STAGEF (2 * 128 * ROWF) // floats per stage (A + B)

__global__ __launch_bounds__(256) void gemm_mma_kernel(float* __restrict__ out) {
    extern __shared__ float sm[];   // [2 stages][A 128*36 | B 128*36]

    int tid = threadIdx.x;
    int wid = tid >> 5;
    int lid = tid & 31;
    int gid = lid >> 2;      // groupID
    int tig = lid & 3;       // threadID_in_group
    int warp_m = wid & 3;    // 0..3
    int warp_n = wid >> 2;   // 0..1
    int n0 = blockIdx.x * GBN;

    int crow = tid >> 1;             // 0..127
    int ccol = (tid & 1) * 16;       // 0 or 16
    const float* asrc0 = g_wt32 + (size_t)crow * KTOT + ccol;
    const float* bsrc0 = g_colT + (size_t)(n0 + crow) * KTOT + ccol;
    uint32_t adst0 = smem_u32(sm) + (uint32_t)(crow * ROWF + ccol) * 4u;
    uint32_t bdst0 = adst0 + 128u * ROWF * 4u;

    float acc[2][8][4];
    #pragma unroll
    for (int mt = 0; mt < 2; ++mt)
        #pragma unroll
        for (int nt = 0; nt < 8; ++nt)
            #pragma unroll
            for (int r = 0; r < 4; ++r) acc[mt][nt][r] = 0.f;

    // prologue: stage 0
    {
        #pragma unroll
        for (int j = 0; j < 4; ++j) {
            CP_ASYNC_CA(adst0 + j * 16u, asrc0 + j * 4);
            CP_ASYNC_CG(bdst0 + j * 16u, bsrc0 + j * 4);
        }
        CP_COMMIT();
    }

    const uint32_t* uA[2];
    const uint32_t* uB[2];
    uA[0] = (const uint32_t*)sm;
    uB[0] = (const uint32_t*)(sm + 128 * ROWF);
    uA[1] = (const uint32_t*)(sm + STAGEF);
    uB[1] = (const uint32_t*)(sm + STAGEF + 128 * ROWF);

    int rA = warp_m * 32 + gid;       // A rows gid, +8, +16, +24
    int nB = warp_n * 64 + gid;       // B rows per n-tile: + nt*8

    for (int t = 0; t < GSTAGES; ++t) {
        if (t + 1 < GSTAGES) {
            int buf = (t + 1) & 1;
            int k0 = (t + 1) * GBK;
            uint32_t ao = adst0 + (uint32_t)buf * STAGEF * 4u;
            uint32_t bo = bdst0 + (uint32_t)buf * STAGEF * 4u;
            #pragma unroll
            for (int j = 0; j < 4; ++j) {
                CP_ASYNC_CA(ao + j * 16u, asrc0 + k0 + j * 4);
                CP_ASYNC_CG(bo + j * 16u, bsrc0 + k0 + j * 4);
            }
            CP_COMMIT();
            CP_WAIT(1);
        } else {
            CP_WAIT(0);
        }
        __syncthreads();

        const uint32_t* As = uA[t & 1];
        const uint32_t* Bs = uB[t & 1];

        #pragma unroll
        for (int ks = 0; ks < 4; ++ks) {
            int k = ks * 8;
            uint32_t a[2][4];
            #pragma unroll
            for (int mt = 0; mt < 2; ++mt) {
                int r0 = rA + mt * 16;
                a[mt][0] = As[r0 * ROWF + k + tig];
                a[mt][1] = As[(r0 + 8) * ROWF + k + tig];
                a[mt][2] = As[r0 * ROWF + k + tig + 4];
                a[mt][3] = As[(r0 + 8) * ROWF + k + tig + 4];
            }
            uint32_t bb[8][2];
            #pragma unroll
            for (int nt = 0; nt < 8; ++nt) {
                int rn = nB + nt * 8;
                bb[nt][0] = Bs[rn * ROWF + k + tig];
                bb[nt][1] = Bs[rn * ROWF + k + tig + 4];
            }
            #pragma unroll
            for (int mt = 0; mt < 2; ++mt)
                #pragma unroll
                for (int nt = 0; nt < 8; ++nt) {
                    asm volatile(
                        "mma.sync.aligned.m16n8k8.row.col.f32.tf32.tf32.f32 "
                        "{%0,%1,%2,%3}, {%4,%5,%6,%7}, {%8,%9}, {%0,%1,%2,%3};"
                        : "+f"(acc[mt][nt][0]), "+f"(acc[mt][nt][1]),
                          "+f"(acc[mt][nt][2]), "+f"(acc[mt][nt][3])
                        : "r"(a[mt][0]), "r"(a[mt][1]), "r"(a[mt][2]), "r"(a[mt][3]),
                          "r"(bb[nt][0]), "r"(bb[nt][1]));
                }
        }
        __syncthreads();
    }

    // epilogue: C[row][col]: rows rA+mt*16+{0,8}, cols warp_n*64+nt*8+2*tig+{0,1}
    #pragma unroll
    for (int mt = 0; mt < 2; ++mt) {
        #pragma unroll
        for (int half = 0; half < 2; ++half) {
            int o = rA + mt * 16 + half * 8;
            #pragma unroll
            for (int nt = 0; nt < 8; ++nt) {
                int np = n0 + warp_n * 64 + nt * 8 + 2 * tig;
                int b   = np / NPIX;
                int pix = np % NPIX;
                float c0 = acc[mt][nt][half * 2 + 0];
                float c1 = acc[mt][nt][half * 2 + 1];
                float* po = out + ((size_t)b * OUTC + o) * NPIX + pix;
                if (pix + 1 < NPIX) {
                    po[0] = c0; po[1] = c1;
                } else {
                    po[0] = c0;
                    int np1 = np + 1;
                    out[((size_t)(np1 / NPIX) * OUTC + o) * NPIX + (np1 % NPIX)] = c1;
                }
            }
        }
    }
}

// ---------------------------------------------------------------------------
extern "C" void kernel_launch(void* const* d_in, const int* in_sizes, int n_in,
                              void* d_out, int out_size) {
    const float* x  = (const float*)d_in[0];
    const float* ow = (const float*)d_in[1];
    const float* ob = (const float*)d_in[2];
    const float* cw = (const float*)d_in[3];
    float* out = (float*)d_out;

    static bool attr_set = false;
    if (!attr_set) {
        cudaFuncSetAttribute(gemm_mma_kernel,
                             cudaFuncAttributeMaxDynamicSharedMemorySize,
                             2 * STAGEF * sizeof(float));
        attr_set = true;
    }

    round_w_kernel<<<(OUTC * KTOT + 1023) / 1024, 1024>>>(cw);
    offset_conv_kernel<<<BATCH * HH, 128>>>(x, ow, ob);
    sample_kernel<<<BATCH * 49, 288>>>(x);
    gemm_mma_kernel<<<NTOT / GBN, 256, 2 * STAGEF * sizeof(float)>>>(out);
}

// round 6
// speedup vs baseline: 2.7952x; 1.1511x over previous
#include <cuda_runtime.h>
#include <cstdint>

// Problem constants
#define CB    128
#define HH    56
#define WW    56
#define NPIX  3136
#define BATCH 8
#define NTOT  25088        // BATCH * NPIX
#define KTOT  1152         // CB * 9
#define OUTC  128

// Scratch
__device__ float g_off2[2][BATCH * 18 * NPIX];  // partial sums (channel halves)
__device__ float g_colT[(size_t)NTOT * KTOT];   // [np][k], tf32-rounded
__device__ float g_wt32[(size_t)OUTC * KTOT];   // tf32-rounded weights

__device__ __forceinline__ float to_tf32(float f) {
    uint32_t u;
    asm("cvt.rna.tf32.f32 %0, %1;" : "=r"(u) : "f"(f));
    return __uint_as_float(u);
}
__device__ __forceinline__ uint32_t smem_u32(const void* p) {
    uint32_t a;
    asm("{ .reg .u64 t; cvta.to.shared.u64 t, %1; cvt.u32.u64 %0, t; }" : "=r"(a) : "l"(p));
    return a;
}
#define CP_ASYNC_CA(dst, src) \
    asm volatile("cp.async.ca.shared.global [%0], [%1], 16;" :: "r"(dst), "l"(src))
#define CP_ASYNC_CG(dst, src) \
    asm volatile("cp.async.cg.shared.global [%0], [%1], 16;" :: "r"(dst), "l"(src))
#define CP_COMMIT() asm volatile("cp.async.commit_group;" ::: "memory")
#define CP_WAIT(n)  asm volatile("cp.async.wait_group %0;" :: "n"(n) : "memory")

// ---------------------------------------------------------------------------
// Kernel 0: round conv weights to tf32
// ---------------------------------------------------------------------------
__global__ void round_w_kernel(const float* __restrict__ w) {
    int i = blockIdx.x * blockDim.x + threadIdx.x;
    if (i < OUTC * KTOT) g_wt32[i] = to_tf32(__ldg(w + i));
}

// ---------------------------------------------------------------------------
// Kernel 1 (v4): offset conv, channel-split. 896 blocks x 128 threads.
// Block = (b, y, half): computes partial sum over 64 channels -> g_off2[half].
// ---------------------------------------------------------------------------
#define OC_CCH 16

__global__ __launch_bounds__(128) void offset_conv_kernel(
        const float* __restrict__ x,
        const float* __restrict__ w,
        const float* __restrict__ bias) {
    __shared__ float xs[OC_CCH][3][60];
    __shared__ float ws[OC_CCH][18][9];

    int blk  = blockIdx.x;
    int half = blk & 1;
    int by   = blk >> 1;
    int b    = by / HH;
    int y    = by % HH;
    int tid  = threadIdx.x;
    int j     = tid / 7;
    int strip = tid % 7;
    bool active = tid < 126;

    for (int e = tid; e < OC_CCH * 3; e += 128) {
        int cc = e / 3, r = e % 3;
        xs[cc][r][0] = 0.f; xs[cc][r][57] = 0.f;
        xs[cc][r][58] = 0.f; xs[cc][r][59] = 0.f;
    }

    float acc[8];
    #pragma unroll
    for (int i = 0; i < 8; ++i) acc[i] = 0.f;

    const float* xb = x + (size_t)b * CB * NPIX;
    int cbeg = half * 64;

    for (int c0 = cbeg; c0 < cbeg + 64; c0 += OC_CCH) {
        __syncthreads();
        for (int e = tid; e < OC_CCH * 3 * WW; e += 128) {
            int cc  = e / (3 * WW);
            int r2  = e % (3 * WW);
            int r   = r2 / WW;
            int col = r2 % WW;
            int yy  = y - 1 + r;
            float v = 0.f;
            if (yy >= 0 && yy < HH)
                v = __ldg(xb + (size_t)(c0 + cc) * NPIX + yy * WW + col);
            xs[cc][r][col + 1] = v;
        }
        for (int e = tid; e < OC_CCH * 162; e += 128) {
            int cc = e / 162;
            int r2 = e % 162;
            ws[cc][r2 / 9][r2 % 9] = __ldg(w + (r2 / 9) * KTOT + (c0 + cc) * 9 + (r2 % 9));
        }
        __syncthreads();

        if (active) {
            #pragma unroll 4
            for (int cc = 0; cc < OC_CCH; ++cc) {
                float wr[9];
                #pragma unroll
                for (int t = 0; t < 9; ++t) wr[t] = ws[cc][j][t];
                #pragma unroll
                for (int ky = 0; ky < 3; ++ky) {
                    float rv[10];
                    #pragma unroll
                    for (int i = 0; i < 10; ++i) rv[i] = xs[cc][ky][strip * 8 + i];
                    #pragma unroll
                    for (int kx = 0; kx < 3; ++kx) {
                        float wv = wr[ky * 3 + kx];
                        #pragma unroll
                        for (int i = 0; i < 8; ++i)
                            acc[i] = fmaf(wv, rv[i + kx], acc[i]);
                    }
                }
            }
        }
    }

    if (active) {
        float bj = half ? 0.f : __ldg(bias + j);
        float* op = g_off2[half] + (size_t)(b * 18 + j) * NPIX + y * WW + strip * 8;
        #pragma unroll
        for (int i = 0; i < 8; ++i) op[i] = acc[i] + bj;
    }
}

// ---------------------------------------------------------------------------
// Kernel 2: deformable sampling -> colT[np][k] (tf32-rounded), k = c*9+n
// Block = (b, 64-pix tile): 392 blocks x 288 threads
// ---------------------------------------------------------------------------
#define SCC 8

__global__ __launch_bounds__(288) void sample_kernel(const float* __restrict__ x) {
    __shared__ float4 ws4[64][9];
    __shared__ int4   os4[64][9];
    __shared__ __align__(16) float vals[64][SCC * 9];

    int b    = blockIdx.x / 49;
    int tile = blockIdx.x % 49;
    int tid  = threadIdx.x;

    for (int e = tid; e < 576; e += 288) {
        int np_l = e / 9, n = e % 9;
        int pix = tile * 64 + np_l;
        int y = pix / WW, xw = pix % WW;

        size_t iy = (size_t)(b * 18 + n) * NPIX + pix;
        size_t ix = (size_t)(b * 18 + n + 9) * NPIX + pix;
        float off_y = g_off2[0][iy] + g_off2[1][iy];
        float off_x = g_off2[0][ix] + g_off2[1][ix];

        float p_y = (float)(y + n / 3) + off_y;
        float p_x = (float)(xw + n % 3) + off_x;

        float qy = floorf(p_y), qx = floorf(p_x);
        float qlt_y = fminf(fmaxf(qy, 0.f), 57.f);
        float qlt_x = fminf(fmaxf(qx, 0.f), 57.f);
        float qrb_y = fminf(fmaxf(qy + 1.f, 0.f), 57.f);
        float qrb_x = fminf(fmaxf(qx + 1.f, 0.f), 57.f);
        float py = fminf(fmaxf(p_y, 0.f), 57.f);
        float px = fminf(fmaxf(p_x, 0.f), 57.f);

        float g_lt = (1.f - (py - qlt_y)) * truncf(1.f - (px - qlt_x));
        float g_rb = (1.f - (qrb_y - py)) * truncf(1.f - (qrb_x - px));
        float g_lb = (1.f - (py - qlt_y)) * (1.f - (qrb_x - px));
        float g_rt = (1.f - (qrb_y - py)) * (1.f - (px - qlt_x));

        int iy_lt = (int)qlt_y, ix_lt = (int)qlt_x;
        int iy_rb = (int)qrb_y, ix_rb = (int)qrb_x;

        int o0 = (iy_lt - 1) * WW + (ix_lt - 1);
        int o1 = (iy_rb - 1) * WW + (ix_rb - 1);
        int o2 = (iy_lt - 1) * WW + (ix_rb - 1);
        int o3 = (iy_rb - 1) * WW + (ix_lt - 1);

        bool vy_lt = (iy_lt >= 1) && (iy_lt <= 56);
        bool vx_lt = (ix_lt >= 1) && (ix_lt <= 56);
        bool vy_rb = (iy_rb >= 1) && (iy_rb <= 56);
        bool vx_rb = (ix_rb >= 1) && (ix_rb <= 56);

        float w0 = (vy_lt && vx_lt) ? g_lt : 0.f;
        float w1 = (vy_rb && vx_rb) ? g_rb : 0.f;
        float w2 = (vy_lt && vx_rb) ? g_lb : 0.f;
        float w3 = (vy_rb && vx_lt) ? g_rt : 0.f;

        ws4[np_l][n] = make_float4(w0, w1, w2, w3);
        os4[np_l][n] = make_int4(o0, o1, o2, o3);
    }
    __syncthreads();

    int e0 = tid, e1 = tid + 288;
    float4 w_a = ws4[e0 / 9][e0 % 9]; int4 o_a = os4[e0 / 9][e0 % 9];
    float4 w_b = ws4[e1 / 9][e1 % 9]; int4 o_b = os4[e1 / 9][e1 % 9];
    int ra = e0 / 9, na = e0 % 9;
    int rb = e1 / 9, nb = e1 % 9;

    const float* xb = x + (size_t)b * CB * NPIX;
    float* colT = g_colT + ((size_t)b * NPIX + (size_t)tile * 64) * KTOT;

    for (int c0 = 0; c0 < CB; c0 += SCC) {
        #pragma unroll
        for (int cc = 0; cc < SCC; ++cc) {
            const float* xc = xb + (size_t)(c0 + cc) * NPIX;
            float v = 0.f;
            if (w_a.x != 0.f) v = fmaf(w_a.x, __ldg(xc + o_a.x), v);
            if (w_a.y != 0.f) v = fmaf(w_a.y, __ldg(xc + o_a.y), v);
            if (w_a.z != 0.f) v = fmaf(w_a.z, __ldg(xc + o_a.z), v);
            if (w_a.w != 0.f) v = fmaf(w_a.w, __ldg(xc + o_a.w), v);
            vals[ra][cc * 9 + na] = to_tf32(v);
            float v2 = 0.f;
            if (w_b.x != 0.f) v2 = fmaf(w_b.x, __ldg(xc + o_b.x), v2);
            if (w_b.y != 0.f) v2 = fmaf(w_b.y, __ldg(xc + o_b.y), v2);
            if (w_b.z != 0.f) v2 = fmaf(w_b.z, __ldg(xc + o_b.z), v2);
            if (w_b.w != 0.f) v2 = fmaf(w_b.w, __ldg(xc + o_b.w), v2);
            vals[rb][cc * 9 + nb] = to_tf32(v2);
        }
        __syncthreads();
        for (int i = tid; i < 64 * 18; i += 288) {
            int row = i / 18, f4 = i % 18;
            *(float4*)(colT + (size_t)row * KTOT + c0 * 9 + f4 * 4) = *(float4*)&vals[row][f4 * 4];
        }
        __syncthreads();
    }
}

// ---------------------------------------------------------------------------
// Kernel 3 (v2): tf32 mma.sync GEMM, 128(M) x 64(N) x 16(K), 3-stage cp.async.
// 392 blocks x 256 thr (8 warps, 4x2; warp tile 32x32). Static smem 46 KB,
// 3 blocks/SM -> whole GEMM is one resident wave.
// ---------------------------------------------------------------------------
#define GBM 128
#define GBN 64
#define GBK 16
#define ROWF 20                         // 16 + 4 pad floats per smem row
#define NSTAGE 3
#define STAGEF ((GBM + GBN) * ROWF)     // 3840 floats
#define NKT (KTOT / GBK)                // 72

__global__ __launch_bounds__(256, 3) void gemm_mma_kernel(float* __restrict__ out) {
    __shared__ float sm[NSTAGE * STAGEF];   // 46080 B

    int tid = threadIdx.x;
    int wid = tid >> 5;
    int lid = tid & 31;
    int gid = lid >> 2;
    int tig = lid & 3;
    int warp_m = wid & 3;    // 0..3 -> 32 M-rows each
    int warp_n = wid >> 2;   // 0..1 -> 32 N-cols each
    int n0 = blockIdx.x * GBN;

    // copy mapping: 64 rows handled per thread-quad chunk
    int crow = tid >> 2;             // 0..63
    int ccol = (tid & 3) * 4;        // 0,4,8,12
    const float* asrc0 = g_wt32 + (size_t)crow * KTOT + ccol;
    const float* asrc1 = asrc0 + (size_t)64 * KTOT;
    const float* bsrc0 = g_colT + (size_t)(n0 + crow) * KTOT + ccol;
    uint32_t smb   = smem_u32(sm);
    uint32_t adst0 = smb + (uint32_t)(crow * ROWF + ccol) * 4u;
    uint32_t adst1 = smb + (uint32_t)((crow + 64) * ROWF + ccol) * 4u;
    uint32_t bdst0 = smb + (uint32_t)((GBM + crow) * ROWF + ccol) * 4u;

    float acc[2][4][4];
    #pragma unroll
    for (int mt = 0; mt < 2; ++mt)
        #pragma unroll
        for (int nt = 0; nt < 4; ++nt)
            #pragma unroll
            for (int r = 0; r < 4; ++r) acc[mt][nt][r] = 0.f;

    // prologue: stages 0 and 1
    #pragma unroll
    for (int s = 0; s < 2; ++s) {
        uint32_t so = (uint32_t)(s * STAGEF) * 4u;
        CP_ASYNC_CA(adst0 + so, asrc0 + s * GBK);
        CP_ASYNC_CA(adst1 + so, asrc1 + s * GBK);
        CP_ASYNC_CG(bdst0 + so, bsrc0 + s * GBK);
        CP_COMMIT();
    }

    int rA = warp_m * 32 + gid;
    int rB = warp_n * 32 + gid;

    for (int t = 0; t < NKT; ++t) {
        if (t + 2 < NKT) {
            int s = (t + 2) % NSTAGE;
            uint32_t so = (uint32_t)(s * STAGEF) * 4u;
            int k0 = (t + 2) * GBK;
            CP_ASYNC_CA(adst0 + so, asrc0 + k0);
            CP_ASYNC_CA(adst1 + so, asrc1 + k0);
            CP_ASYNC_CG(bdst0 + so, bsrc0 + k0);
        }
        CP_COMMIT();
        CP_WAIT(2);
        __syncthreads();

        const float* stg = sm + (t % NSTAGE) * STAGEF;
        const uint32_t* As = (const uint32_t*)stg;
        const uint32_t* Bs = (const uint32_t*)(stg + GBM * ROWF);

        #pragma unroll
        for (int ks = 0; ks < 2; ++ks) {
            int k = ks * 8;
            uint32_t a[2][4];
            #pragma unroll
            for (int mt = 0; mt < 2; ++mt) {
                int r0 = rA + mt * 16;
                a[mt][0] = As[r0 * ROWF + k + tig];
                a[mt][1] = As[(r0 + 8) * ROWF + k + tig];
                a[mt][2] = As[r0 * ROWF + k + tig + 4];
                a[mt][3] = As[(r0 + 8) * ROWF + k + tig + 4];
            }
            uint32_t bb[4][2];
            #pragma unroll
            for (int nt = 0; nt < 4; ++nt) {
                int rn = rB + nt * 8;
                bb[nt][0] = Bs[rn * ROWF + k + tig];
                bb[nt][1] = Bs[rn * ROWF + k + tig + 4];
            }
            #pragma unroll
            for (int mt = 0; mt < 2; ++mt)
                #pragma unroll
                for (int nt = 0; nt < 4; ++nt) {
                    asm volatile(
                        "mma.sync.aligned.m16n8k8.row.col.f32.tf32.tf32.f32 "
                        "{%0,%1,%2,%3}, {%4,%5,%6,%7}, {%8,%9}, {%0,%1,%2,%3};"
                        : "+f"(acc[mt][nt][0]), "+f"(acc[mt][nt][1]),
                          "+f"(acc[mt][nt][2]), "+f"(acc[mt][nt][3])
                        : "r"(a[mt][0]), "r"(a[mt][1]), "r"(a[mt][2]), "r"(a[mt][3]),
                          "r"(bb[nt][0]), "r"(bb[nt][1]));
                }
        }
        __syncthreads();
    }

    // epilogue: 64-wide N tile never crosses a batch boundary (64 | NPIX)
    int b   = n0 / NPIX;
    int px0 = n0 % NPIX;
    #pragma unroll
    for (int mt = 0; mt < 2; ++mt) {
        #pragma unroll
        for (int half = 0; half < 2; ++half) {
            int o = rA + mt * 16 + half * 8;
            float* po = out + ((size_t)b * OUTC + o) * NPIX + px0;
            #pragma unroll
            for (int nt = 0; nt < 4; ++nt) {
                int col = warp_n * 32 + nt * 8 + 2 * tig;
                float2 v = make_float2(acc[mt][nt][half * 2], acc[mt][nt][half * 2 + 1]);
                *(float2*)(po + col) = v;
            }
        }
    }
}

// ---------------------------------------------------------------------------
extern "C" void kernel_launch(void* const* d_in, const int* in_sizes, int n_in,
                              void* d_out, int out_size) {
    const float* x  = (const float*)d_in[0];
    const float* ow = (const float*)d_in[1];
    const float* ob = (const float*)d_in[2];
    const float* cw = (const float*)d_in[3];
    float* out = (float*)d_out;

    round_w_kernel<<<(OUTC * KTOT + 1023) / 1024, 1024>>>(cw);
    offset_conv_kernel<<<BATCH * HH * 2, 128>>>(x, ow, ob);
    sample_kernel<<<BATCH * 49, 288>>>(x);
    gemm_mma_kernel<<<NTOT / GBN, 256>>>(out);
}

// round 8
// speedup vs baseline: 2.8514x; 1.0201x over previous
#include <cuda_runtime.h>
#include <cstdint>

// Problem constants
#define CB    128
#define HH    56
#define WW    56
#define NPIX  3136
#define BATCH 8
#define NTOT  25088        // BATCH * NPIX
#define KTOT  1152         // CB * 9
#define OUTC  128

// Scratch
__device__ float g_off2[2][BATCH * 18 * NPIX];  // offset conv partial sums
__device__ float g_wt32[(size_t)OUTC * KTOT];   // tf32 weights, k' = n*128 + c

__device__ __forceinline__ float to_tf32(float f) {
    uint32_t u;
    asm("cvt.rna.tf32.f32 %0, %1;" : "=r"(u) : "f"(f));
    return __uint_as_float(u);
}
__device__ __forceinline__ uint32_t smem_u32(const void* p) {
    uint32_t a;
    asm("{ .reg .u64 t; cvta.to.shared.u64 t, %1; cvt.u32.u64 %0, t; }" : "=r"(a) : "l"(p));
    return a;
}
#define CP_ASYNC_CA(dst, src) \
    asm volatile("cp.async.ca.shared.global [%0], [%1], 16;" :: "r"(dst), "l"(src))
#define CP_COMMIT() asm volatile("cp.async.commit_group;" ::: "memory")
#define CP_WAIT(n)  asm volatile("cp.async.wait_group %0;" :: "n"(n) : "memory")

// ---------------------------------------------------------------------------
// Kernel 0: round weights to tf32 AND permute k: c*9+n -> n*128+c
// ---------------------------------------------------------------------------
__global__ void round_w_kernel(const float* __restrict__ w) {
    int i = blockIdx.x * blockDim.x + threadIdx.x;   // i = o*KTOT + c*9 + n
    if (i >= OUTC * KTOT) return;
    int o = i / KTOT;
    int r = i % KTOT;
    int c = r / 9;
    int n = r % 9;
    g_wt32[(size_t)o * KTOT + n * 128 + c] = to_tf32(__ldg(w + i));
}

// ---------------------------------------------------------------------------
// Kernel 1: offset conv, channel-split. 896 blocks x 128 threads.
// ---------------------------------------------------------------------------
#define OC_CCH 16

__global__ __launch_bounds__(128) void offset_conv_kernel(
        const float* __restrict__ x,
        const float* __restrict__ w,
        const float* __restrict__ bias) {
    __shared__ float xs[OC_CCH][3][60];
    __shared__ float ws[OC_CCH][18][9];

    int blk  = blockIdx.x;
    int half = blk & 1;
    int by   = blk >> 1;
    int b    = by / HH;
    int y    = by % HH;
    int tid  = threadIdx.x;
    int j     = tid / 7;
    int strip = tid % 7;
    bool active = tid < 126;

    for (int e = tid; e < OC_CCH * 3; e += 128) {
        int cc = e / 3, r = e % 3;
        xs[cc][r][0] = 0.f; xs[cc][r][57] = 0.f;
        xs[cc][r][58] = 0.f; xs[cc][r][59] = 0.f;
    }

    float acc[8];
    #pragma unroll
    for (int i = 0; i < 8; ++i) acc[i] = 0.f;

    const float* xb = x + (size_t)b * CB * NPIX;
    int cbeg = half * 64;

    for (int c0 = cbeg; c0 < cbeg + 64; c0 += OC_CCH) {
        __syncthreads();
        for (int e = tid; e < OC_CCH * 3 * WW; e += 128) {
            int cc  = e / (3 * WW);
            int r2  = e % (3 * WW);
            int r   = r2 / WW;
            int col = r2 % WW;
            int yy  = y - 1 + r;
            float v = 0.f;
            if (yy >= 0 && yy < HH)
                v = __ldg(xb + (size_t)(c0 + cc) * NPIX + yy * WW + col);
            xs[cc][r][col + 1] = v;
        }
        for (int e = tid; e < OC_CCH * 162; e += 128) {
            int cc = e / 162;
            int r2 = e % 162;
            ws[cc][r2 / 9][r2 % 9] = __ldg(w + (r2 / 9) * KTOT + (c0 + cc) * 9 + (r2 % 9));
        }
        __syncthreads();

        if (active) {
            #pragma unroll 4
            for (int cc = 0; cc < OC_CCH; ++cc) {
                float wr[9];
                #pragma unroll
                for (int t = 0; t < 9; ++t) wr[t] = ws[cc][j][t];
                #pragma unroll
                for (int ky = 0; ky < 3; ++ky) {
                    float rv[10];
                    #pragma unroll
                    for (int i = 0; i < 10; ++i) rv[i] = xs[cc][ky][strip * 8 + i];
                    #pragma unroll
                    for (int kx = 0; kx < 3; ++kx) {
                        float wv = wr[ky * 3 + kx];
                        #pragma unroll
                        for (int i = 0; i < 8; ++i)
                            acc[i] = fmaf(wv, rv[i + kx], acc[i]);
                    }
                }
            }
        }
    }

    if (active) {
        float bj = half ? 0.f : __ldg(bias + j);
        float* op = g_off2[half] + (size_t)(b * 18 + j) * NPIX + y * WW + strip * 8;
        #pragma unroll
        for (int i = 0; i < 8; ++i) op[i] = acc[i] + bj;
    }
}

// ---------------------------------------------------------------------------
// Kernel 2: FUSED sample + tf32 mma GEMM (race-fixed pipeline).
// Per iter: build B(t) [pre-sync] -> CP_WAIT(0) -> sync -> issue A(t+1)
// [post-sync => WAR-safe vs iter t-1 readers] -> mma(t).
// ---------------------------------------------------------------------------
#define ROWF_A 20
#define ROWF_B 20
#define NCHUNK 72

__global__ __launch_bounds__(256, 3) void fused_gemm_kernel(
        const float* __restrict__ x, float* __restrict__ out) {
    __shared__ float4 wsm[64][9];                  // 9216 B
    __shared__ int4   osm[64][9];                  // 9216 B
    __shared__ float  As[2][128][ROWF_A];          // 20480 B
    __shared__ float  Bs[2][64][ROWF_B];           // 10240 B   total 49152 B

    int tid  = threadIdx.x;
    int wid  = tid >> 5;
    int lid  = tid & 31;
    int gid  = lid >> 2;
    int tig  = lid & 3;
    int warp_m = wid & 3;
    int warp_n = wid >> 2;

    int b    = blockIdx.x / 49;
    int tile = blockIdx.x % 49;
    int px0  = tile * 64;

    const float* xb = x + (size_t)b * CB * NPIX;

    // ---------------- Phase A: bilinear weight/offset tables ----------------
    for (int e = tid; e < 576; e += 256) {
        int np_l = e / 9, n = e % 9;
        int pix = px0 + np_l;
        int y = pix / WW, xw = pix % WW;

        size_t iy = (size_t)(b * 18 + n) * NPIX + pix;
        size_t ix = (size_t)(b * 18 + n + 9) * NPIX + pix;
        float off_y = g_off2[0][iy] + g_off2[1][iy];
        float off_x = g_off2[0][ix] + g_off2[1][ix];

        float p_y = (float)(y + n / 3) + off_y;
        float p_x = (float)(xw + n % 3) + off_x;

        float qy = floorf(p_y), qx = floorf(p_x);
        float qlt_y = fminf(fmaxf(qy, 0.f), 57.f);
        float qlt_x = fminf(fmaxf(qx, 0.f), 57.f);
        float qrb_y = fminf(fmaxf(qy + 1.f, 0.f), 57.f);
        float qrb_x = fminf(fmaxf(qx + 1.f, 0.f), 57.f);
        float py = fminf(fmaxf(p_y, 0.f), 57.f);
        float px = fminf(fmaxf(p_x, 0.f), 57.f);

        float g_lt = (1.f - (py - qlt_y)) * truncf(1.f - (px - qlt_x));
        float g_rb = (1.f - (qrb_y - py)) * truncf(1.f - (qrb_x - px));
        float g_lb = (1.f - (py - qlt_y)) * (1.f - (qrb_x - px));
        float g_rt = (1.f - (qrb_y - py)) * (1.f - (px - qlt_x));

        int iy_lt = (int)qlt_y, ix_lt = (int)qlt_x;
        int iy_rb = (int)qrb_y, ix_rb = (int)qrb_x;

        int o0 = (iy_lt - 1) * WW + (ix_lt - 1);
        int o1 = (iy_rb - 1) * WW + (ix_rb - 1);
        int o2 = (iy_lt - 1) * WW + (ix_rb - 1);
        int o3 = (iy_rb - 1) * WW + (ix_lt - 1);

        bool vy_lt = (iy_lt >= 1) && (iy_lt <= 56);
        bool vx_lt = (ix_lt >= 1) && (ix_lt <= 56);
        bool vy_rb = (iy_rb >= 1) && (iy_rb <= 56);
        bool vx_rb = (ix_rb >= 1) && (ix_rb <= 56);

        float w0 = (vy_lt && vx_lt) ? g_lt : 0.f;
        float w1 = (vy_rb && vx_rb) ? g_rb : 0.f;
        float w2 = (vy_lt && vx_rb) ? g_lb : 0.f;
        float w3 = (vy_rb && vx_lt) ? g_rt : 0.f;

        wsm[np_l][n] = make_float4(w0, w1, w2, w3);
        osm[np_l][n] = make_int4(o0, o1, o2, o3);
    }

    // A copy addressing: 2 x cp.async(16B) per thread per chunk
    int ar0 = tid >> 2;                 // rows 0..63 (+64 for second op)
    int ac0 = (tid & 3) * 4;            // 0,4,8,12
    const float* asrc0 = g_wt32 + (size_t)ar0 * KTOT + ac0;
    const float* asrc1 = asrc0 + (size_t)64 * KTOT;
    uint32_t smb = smem_u32(&As[0][0][0]);
    uint32_t adst0 = smb + (uint32_t)(ar0 * ROWF_A + ac0) * 4u;
    uint32_t adst1 = smb + (uint32_t)((ar0 + 64) * ROWF_A + ac0) * 4u;
    const uint32_t ASTAGE = 128u * ROWF_A * 4u;

    // B build addressing: thread -> np = tid/4, channel group = tid%4
    int bnp = tid >> 2;
    int bcg = tid & 3;

    float acc[2][4][4];
    #pragma unroll
    for (int mt = 0; mt < 2; ++mt)
        #pragma unroll
        for (int nt = 0; nt < 4; ++nt)
            #pragma unroll
            for (int r = 0; r < 4; ++r) acc[mt][nt][r] = 0.f;

    // prologue: A chunk 0 (no hazard: nothing has read As yet)
    CP_ASYNC_CA(adst0, asrc0);
    CP_ASYNC_CA(adst1, asrc1);
    CP_COMMIT();
    __syncthreads();    // tables ready

    int rA = warp_m * 32 + gid;
    int rB = warp_n * 32 + gid;

    for (int t = 0; t < NCHUNK; ++t) {
        int buf = t & 1;

        // build B tile (pre-sync; readers of this buffer finished before the
        // barrier of iter t-1, which we have passed): n = t/8, 16 channels
        {
            int n  = t >> 3;
            int c0 = (t & 7) * 16 + bcg * 4;
            float4 w4 = wsm[bnp][n];
            int4   o4 = osm[bnp][n];
            const float* xc = xb + (size_t)c0 * NPIX;
            float v[4];
            #pragma unroll
            for (int i = 0; i < 4; ++i) {
                const float* xi = xc + (size_t)i * NPIX;
                float s = 0.f;
                if (w4.x != 0.f) s = fmaf(w4.x, __ldg(xi + o4.x), s);
                if (w4.y != 0.f) s = fmaf(w4.y, __ldg(xi + o4.y), s);
                if (w4.z != 0.f) s = fmaf(w4.z, __ldg(xi + o4.z), s);
                if (w4.w != 0.f) s = fmaf(w4.w, __ldg(xi + o4.w), s);
                v[i] = to_tf32(s);
            }
            *(float4*)&Bs[buf][bnp][bcg * 4] = make_float4(v[0], v[1], v[2], v[3]);
        }

        CP_WAIT(0);          // chunk t landed (issued one full iteration ago)
        __syncthreads();

        // A prefetch AFTER the barrier: iter t-1 readers of As[(t+1)&1] are
        // provably done (they arrived at this barrier). WAR-safe.
        if (t + 1 < NCHUNK) {
            uint32_t so = (uint32_t)((t + 1) & 1) * ASTAGE;
            CP_ASYNC_CA(adst0 + so, asrc0 + (t + 1) * 16);
            CP_ASYNC_CA(adst1 + so, asrc1 + (t + 1) * 16);
            CP_COMMIT();
        }

        const uint32_t* Asu = (const uint32_t*)&As[buf][0][0];
        const uint32_t* Bsu = (const uint32_t*)&Bs[buf][0][0];

        #pragma unroll
        for (int ks = 0; ks < 2; ++ks) {
            int k = ks * 8;
            uint32_t a[2][4];
            #pragma unroll
            for (int mt = 0; mt < 2; ++mt) {
                int r0 = rA + mt * 16;
                a[mt][0] = Asu[r0 * ROWF_A + k + tig];
                a[mt][1] = Asu[(r0 + 8) * ROWF_A + k + tig];
                a[mt][2] = Asu[r0 * ROWF_A + k + tig + 4];
                a[mt][3] = Asu[(r0 + 8) * ROWF_A + k + tig + 4];
            }
            uint32_t bb[4][2];
            #pragma unroll
            for (int nt = 0; nt < 4; ++nt) {
                int rn = rB + nt * 8;
                bb[nt][0] = Bsu[rn * ROWF_B + k + tig];
                bb[nt][1] = Bsu[rn * ROWF_B + k + tig + 4];
            }
            #pragma unroll
            for (int mt = 0; mt < 2; ++mt)
                #pragma unroll
                for (int nt = 0; nt < 4; ++nt) {
                    asm volatile(
                        "mma.sync.aligned.m16n8k8.row.col.f32.tf32.tf32.f32 "
                        "{%0,%1,%2,%3}, {%4,%5,%6,%7}, {%8,%9}, {%0,%1,%2,%3};"
                        : "+f"(acc[mt][nt][0]), "+f"(acc[mt][nt][1]),
                          "+f"(acc[mt][nt][2]), "+f"(acc[mt][nt][3])
                        : "r"(a[mt][0]), "r"(a[mt][1]), "r"(a[mt][2]), "r"(a[mt][3]),
                          "r"(bb[nt][0]), "r"(bb[nt][1]));
                }
        }
    }

    // epilogue
    #pragma unroll
    for (int mt = 0; mt < 2; ++mt) {
        #pragma unroll
        for (int half = 0; half < 2; ++half) {
            int o = rA + mt * 16 + half * 8;
            float* po = out + ((size_t)b * OUTC + o) * NPIX + px0;
            #pragma unroll
            for (int nt = 0; nt < 4; ++nt) {
                int col = warp_n * 32 + nt * 8 + 2 * tig;
                float2 v = make_float2(acc[mt][nt][half * 2], acc[mt][nt][half * 2 + 1]);
                *(float2*)(po + col) = v;
            }
        }
    }
}

// ---------------------------------------------------------------------------
extern "C" void kernel_launch(void* const* d_in, const int* in_sizes, int n_in,
                              void* d_out, int out_size) {
    const float* x  = (const float*)d_in[0];
    const float* ow = (const float*)d_in[1];
    const float* ob = (const float*)d_in[2];
    const float* cw = (const float*)d_in[3];
    float* out = (float*)d_out;

    round_w_kernel<<<(OUTC * KTOT + 1023) / 1024, 1024>>>(cw);
    offset_conv_kernel<<<BATCH * HH * 2, 128>>>(x, ow, ob);
    fused_gemm_kernel<<<NTOT / 64, 256>>>(x, out);
}